// round 1
// baseline (speedup 1.0000x reference)
#include <cuda_runtime.h>
#include <stdint.h>

#define Dm 256
#define Bm 16384
#define NSTEPS 5
#define Mrows 16
#define NW 8

// ---- flag-independent accurate fp32 exp/log/sigmoid (pure FMA + __fdiv_rn) ----

static __device__ __forceinline__ float my_exp(float x) {
    x = fmaxf(x, -80.0f);
    float z = x * 1.4426950408889634f;
    float n = rintf(z);
    float r = fmaf(n, -0.693359375f, x);
    r = fmaf(n, 2.12194440054690583e-4f, r);
    float p = 1.9841269841269841e-4f;          // 1/5040
    p = fmaf(p, r, 1.3888888888888889e-3f);    // 1/720
    p = fmaf(p, r, 8.3333333333333333e-3f);    // 1/120
    p = fmaf(p, r, 4.1666666666666664e-2f);    // 1/24
    p = fmaf(p, r, 1.6666666666666666e-1f);    // 1/6
    p = fmaf(p, r, 0.5f);
    p = fmaf(p, r, 1.0f);
    p = fmaf(p, r, 1.0f);
    int ni = (int)n;
    return p * __int_as_float((127 + ni) << 23);
}

static __device__ __forceinline__ float my_log(float v) {
    int i = __float_as_int(v);
    int e = (i - 0x3f3504f3) >> 23;
    float m = __int_as_float(i - (e << 23));   // m in [0.7071, 1.4142)
    float f = m - 1.0f;
    float s = __fdiv_rn(f, 2.0f + f);
    float s2 = s * s;
    float p = 0.22222222f;                     // 2/9
    p = fmaf(p, s2, 0.28571429f);              // 2/7
    p = fmaf(p, s2, 0.4f);                     // 2/5
    p = fmaf(p, s2, 0.66666667f);              // 2/3
    float logm = fmaf(p * s2, s, 2.0f * s);    // 2*atanh(s)
    float ef = (float)e;
    return fmaf(ef, 0.693359375f, fmaf(ef, -2.12194440054690583e-4f, logm));
}

static __device__ __forceinline__ float my_sigmoid(float t) {
    float en = my_exp(-fabsf(t));
    float s = __fdiv_rn(en, 1.0f + en);
    return (t > 0.0f) ? 1.0f - s : s;
}

// ---- fused sampler: one block = 16 independent chains, thread d owns dim d ----

__global__ void __launch_bounds__(256, 2)
els_kernel(const float* __restrict__ x_in, const float* __restrict__ xa_in,
           const float* __restrict__ Wm, const float* __restrict__ bv,
           const float* __restrict__ rr, const float* __restrict__ noise,
           const float* __restrict__ au, float* __restrict__ out)
{
    const int d = threadIdx.x;
    const int warp = d >> 5;
    const int lane = d & 31;
    const int rowBase = blockIdx.x * Mrows;

    __shared__ float xs[Dm][Mrows];            // x as floats, [e][m] for init GEMM
    __shared__ unsigned posw[Mrows][NW];       // flip 0->1 bitmasks per 32-e chunk
    __shared__ unsigned negw[Mrows][NW];       // flip 1->0 bitmasks
    __shared__ float red[Mrows][NW];           // per-warp partial la
    __shared__ float accs[Mrows];              // accept flags

    const float bd = bv[d];
    float xa[Mrows], h[Mrows];
    unsigned xmask = 0;

    #pragma unroll
    for (int m = 0; m < Mrows; m++) {
        float xv = x_in[(size_t)(rowBase + m) * Dm + d];
        xa[m] = xa_in[(size_t)(rowBase + m) * Dm + d];
        xs[d][m] = xv;
        if (xv != 0.0f) xmask |= (1u << m);
        h[m] = 0.0f;
    }
    __syncthreads();

    // init: h[m] = (x[m] @ W)[d]   rank-1 update sweep, x broadcast from smem
    #pragma unroll 2
    for (int e = 0; e < Dm; e++) {
        float w = Wm[e * Dm + d];
        const float4* xp = reinterpret_cast<const float4*>(xs[e]);
        float4 a0 = xp[0], a1 = xp[1], a2 = xp[2], a3 = xp[3];
        h[0]  = fmaf(a0.x, w, h[0]);   h[1]  = fmaf(a0.y, w, h[1]);
        h[2]  = fmaf(a0.z, w, h[2]);   h[3]  = fmaf(a0.w, w, h[3]);
        h[4]  = fmaf(a1.x, w, h[4]);   h[5]  = fmaf(a1.y, w, h[5]);
        h[6]  = fmaf(a1.z, w, h[6]);   h[7]  = fmaf(a1.w, w, h[7]);
        h[8]  = fmaf(a2.x, w, h[8]);   h[9]  = fmaf(a2.y, w, h[9]);
        h[10] = fmaf(a2.z, w, h[10]);  h[11] = fmaf(a2.w, w, h[11]);
        h[12] = fmaf(a3.x, w, h[12]);  h[13] = fmaf(a3.y, w, h[13]);
        h[14] = fmaf(a3.z, w, h[14]);  h[15] = fmaf(a3.w, w, h[15]);
    }

    for (int step = 0; step < NSTEPS; step++) {
        float xda[Mrows], h2[Mrows], tacc[Mrows];
        unsigned indmask = 0;

        // ---- stage 1: propose flips, forward log-prob terms ----
        #pragma unroll
        for (int m = 0; m < Mrows; m++) {
            float xf  = ((xmask >> m) & 1u) ? 1.0f : 0.0f;
            float sgn = 1.0f - 2.0f * xf;                    // -(2x-1)
            float ga  = (xf - xa[m]) * 1e-4f;                // (x - xa)/ETA
            float hb  = h[m] + bd;
            float gm  = (hb * sgn) * 0.5f - (ga * 0.5f) * sgn;
            float fp  = my_sigmoid(gm - 2.5f);
            float rv  = rr[((size_t)(step * Bm + rowBase + m)) * Dm + d];
            bool ind  = rv < fp;
            float nv  = noise[((size_t)(step * Bm + rowBase + m)) * Dm + d];
            float inner = xa[m] + 0.25f * ga;                // 0.25*ga exact
            float pn  = __fmul_rn(0.70710678118654752f, nv); // keep two roundings like ref
            float xdav = inner + pn;
            float lpf = my_log((ind ? fp : 1.0f - fp) + 1e-10f);
            float e1  = (xf != 0.0f) ? fmaf(0.5f, h[m], bd) : 0.0f;  // x*(0.5h+b)
            float dxa = xf - xa[m];
            float q1  = xdav - inner;                        // fwd residual
            tacc[m] = fmaf(dxa * dxa, 5e-5f, q1 * q1) - lpf - e1;
            if (ind) indmask |= (1u << m);
            unsigned pb = __ballot_sync(0xffffffffu, ind && xf == 0.0f);
            unsigned nb = __ballot_sync(0xffffffffu, ind && xf != 0.0f);
            if (lane == 0) { posw[m][warp] = pb; negw[m][warp] = nb; }
            xda[m] = xdav;
        }
        __syncthreads();

        // ---- stage 2+3: incremental h2, reverse terms, per-row la reduce ----
        #pragma unroll
        for (int m = 0; m < Mrows; m++) {
            float acc = h[m];
            #pragma unroll
            for (int c = 0; c < NW; c++) {
                unsigned pw = posw[m][c];
                while (pw) {
                    int j = __ffs(pw) - 1; pw &= pw - 1;
                    acc += Wm[(c * 32 + j) * Dm + d];
                }
                unsigned nw_ = negw[m][c];
                while (nw_) {
                    int j = __ffs(nw_) - 1; nw_ &= nw_ - 1;
                    acc -= Wm[(c * 32 + j) * Dm + d];
                }
            }
            h2[m] = acc;

            float xf   = ((xmask >> m) & 1u) ? 1.0f : 0.0f;
            bool  ind  = (indmask >> m) & 1u;
            float xdv  = ind ? 1.0f - xf : xf;
            float sgn2 = 1.0f - 2.0f * xdv;
            float ga2  = (xdv - xda[m]) * 1e-4f;
            float hb2  = acc + bd;
            float gm2  = (hb2 * sgn2) * 0.5f - (ga2 * 0.5f) * sgn2;
            float fp2  = my_sigmoid(gm2 - 2.5f);
            float lpr  = my_log((ind ? fp2 : 1.0f - fp2) + 1e-10f);
            float e2   = (xdv != 0.0f) ? fmaf(0.5f, acc, bd) : 0.0f;
            float dxd  = xdv - xda[m];
            float inner2 = fmaf(0.25f, ga2, xda[m]);
            float q2   = xa[m] - inner2;                     // rev residual
            float t = tacc[m] + lpr + e2 - fmaf(dxd * dxd, 5e-5f, q2 * q2);

            t += __shfl_down_sync(0xffffffffu, t, 16);
            t += __shfl_down_sync(0xffffffffu, t, 8);
            t += __shfl_down_sync(0xffffffffu, t, 4);
            t += __shfl_down_sync(0xffffffffu, t, 2);
            t += __shfl_down_sync(0xffffffffu, t, 1);
            if (lane == 0) red[m][warp] = t;
        }
        __syncthreads();

        // ---- MH accept per row ----
        if (d < Mrows) {
            float la = 0.0f;
            #pragma unroll
            for (int w2 = 0; w2 < NW; w2++) la += red[d][w2];
            float u = au[step * Bm + rowBase + d];
            float lu = (u > 0.0f) ? my_log(u) : -3.0e38f;
            accs[d] = (la > lu) ? 1.0f : 0.0f;
        }
        __syncthreads();

        // ---- commit ----
        #pragma unroll
        for (int m = 0; m < Mrows; m++) {
            if (accs[m] != 0.0f) {
                xa[m] = xda[m];
                h[m]  = h2[m];
                xmask ^= (indmask & (1u << m));
            }
        }
        __syncthreads();
    }

    #pragma unroll
    for (int m = 0; m < Mrows; m++) {
        float xf = ((xmask >> m) & 1u) ? 1.0f : 0.0f;
        out[(size_t)(rowBase + m) * Dm + d] = xf;
        out[(size_t)Bm * Dm + (size_t)(rowBase + m) * Dm + d] = xa[m];
    }
}

extern "C" void kernel_launch(void* const* d_in, const int* in_sizes, int n_in,
                              void* d_out, int out_size) {
    const float* x  = (const float*)d_in[0];
    const float* xa = (const float*)d_in[1];
    const float* W  = (const float*)d_in[2];
    const float* b  = (const float*)d_in[3];
    const float* rr = (const float*)d_in[4];
    const float* nz = (const float*)d_in[5];
    const float* au = (const float*)d_in[6];
    els_kernel<<<Bm / Mrows, 256>>>(x, xa, W, b, rr, nz, au, (float*)d_out);
}

// round 2
// speedup vs baseline: 1.7065x; 1.7065x over previous
#include <cuda_runtime.h>
#include <stdint.h>

#define Dm 256
#define Bm 16384
#define NSTEPS 5
#define Mrows 16
#define NW 8
#define LCAP 264   // max 256 flips + pad to multiple of 8

// ---- flag-independent accurate fp32 exp/log/sigmoid (pure FMA + __fdiv_rn) ----

static __device__ __forceinline__ float my_exp(float x) {
    x = fmaxf(x, -80.0f);
    float z = x * 1.4426950408889634f;
    float n = rintf(z);
    float r = fmaf(n, -0.693359375f, x);
    r = fmaf(n, 2.12194440054690583e-4f, r);
    float p = 1.9841269841269841e-4f;
    p = fmaf(p, r, 1.3888888888888889e-3f);
    p = fmaf(p, r, 8.3333333333333333e-3f);
    p = fmaf(p, r, 4.1666666666666664e-2f);
    p = fmaf(p, r, 1.6666666666666666e-1f);
    p = fmaf(p, r, 0.5f);
    p = fmaf(p, r, 1.0f);
    p = fmaf(p, r, 1.0f);
    int ni = (int)n;
    return p * __int_as_float((127 + ni) << 23);
}

static __device__ __forceinline__ float my_log(float v) {
    int i = __float_as_int(v);
    int e = (i - 0x3f3504f3) >> 23;
    float m = __int_as_float(i - (e << 23));
    float f = m - 1.0f;
    float s = __fdiv_rn(f, 2.0f + f);
    float s2 = s * s;
    float p = 0.22222222f;
    p = fmaf(p, s2, 0.28571429f);
    p = fmaf(p, s2, 0.4f);
    p = fmaf(p, s2, 0.66666667f);
    float logm = fmaf(p * s2, s, 2.0f * s);
    float ef = (float)e;
    return fmaf(ef, 0.693359375f, fmaf(ef, -2.12194440054690583e-4f, logm));
}

static __device__ __forceinline__ float my_sigmoid(float t) {
    float en = my_exp(-fabsf(t));
    float s = __fdiv_rn(en, 1.0f + en);
    return (t > 0.0f) ? 1.0f - s : s;
}

// ---- fused sampler: one block = 16 independent chains, thread d owns dim d ----

__global__ void __launch_bounds__(256, 2)
els_kernel(const float* __restrict__ x_in, const float* __restrict__ xa_in,
           const float* __restrict__ Wm, const float* __restrict__ bv,
           const float* __restrict__ rr, const float* __restrict__ noise,
           const float* __restrict__ au, float* __restrict__ out)
{
    const int d = threadIdx.x;
    const int warp = d >> 5;
    const int lane = d & 31;
    const int rowBase = blockIdx.x * Mrows;

    __shared__ float xs[Dm][Mrows];            // x as floats (init GEMM only)
    __shared__ unsigned posw[Mrows][NW];       // flip 0->1 bitmasks per 32-e chunk
    __shared__ unsigned negw[Mrows][NW];       // flip 1->0 bitmasks
    __shared__ short   flist[Mrows][LCAP];     // signed flip index list (bit8 = neg, 512 = pad)
    __shared__ int     fcnt[Mrows];            // padded list length
    __shared__ float   red[Mrows][NW];         // per-warp partial la
    __shared__ float   accs[Mrows];            // accept flags

    const float bd = bv[d];
    float xa[Mrows], h[Mrows];
    unsigned xmask = 0;

    #pragma unroll
    for (int m = 0; m < Mrows; m++) {
        float xv = x_in[(size_t)(rowBase + m) * Dm + d];
        xa[m] = xa_in[(size_t)(rowBase + m) * Dm + d];
        xs[d][m] = xv;
        if (xv != 0.0f) xmask |= (1u << m);
        h[m] = 0.0f;
    }
    __syncthreads();

    // init: h[m] = (x[m] @ W)[d]   rank-1 update sweep, x broadcast from smem
    #pragma unroll 2
    for (int e = 0; e < Dm; e++) {
        float w = Wm[e * Dm + d];
        const float4* xp = reinterpret_cast<const float4*>(xs[e]);
        float4 a0 = xp[0], a1 = xp[1], a2 = xp[2], a3 = xp[3];
        h[0]  = fmaf(a0.x, w, h[0]);   h[1]  = fmaf(a0.y, w, h[1]);
        h[2]  = fmaf(a0.z, w, h[2]);   h[3]  = fmaf(a0.w, w, h[3]);
        h[4]  = fmaf(a1.x, w, h[4]);   h[5]  = fmaf(a1.y, w, h[5]);
        h[6]  = fmaf(a1.z, w, h[6]);   h[7]  = fmaf(a1.w, w, h[7]);
        h[8]  = fmaf(a2.x, w, h[8]);   h[9]  = fmaf(a2.y, w, h[9]);
        h[10] = fmaf(a2.z, w, h[10]);  h[11] = fmaf(a2.w, w, h[11]);
        h[12] = fmaf(a3.x, w, h[12]);  h[13] = fmaf(a3.y, w, h[13]);
        h[14] = fmaf(a3.z, w, h[14]);  h[15] = fmaf(a3.w, w, h[15]);
    }

    for (int step = 0; step < NSTEPS; step++) {
        float xda[Mrows], h2[Mrows], tacc[Mrows];
        unsigned indmask = 0;

        // ---- stage 1: propose flips, forward log-prob terms ----
        #pragma unroll
        for (int m = 0; m < Mrows; m++) {
            float xf  = ((xmask >> m) & 1u) ? 1.0f : 0.0f;
            float sgn = 1.0f - 2.0f * xf;                    // -(2x-1)
            float ga  = (xf - xa[m]) * 1e-4f;                // (x - xa)/ETA
            float hb  = h[m] + bd;
            float gm  = (hb * sgn) * 0.5f - (ga * 0.5f) * sgn;
            float fp  = my_sigmoid(gm - 2.5f);
            float rv  = rr[((size_t)(step * Bm + rowBase + m)) * Dm + d];
            bool ind  = rv < fp;
            float nv  = noise[((size_t)(step * Bm + rowBase + m)) * Dm + d];
            float inner = xa[m] + 0.25f * ga;
            float pn  = __fmul_rn(0.70710678118654752f, nv);
            float xdav = inner + pn;
            float lpf = my_log((ind ? fp : 1.0f - fp) + 1e-10f);
            float e1  = (xf != 0.0f) ? fmaf(0.5f, h[m], bd) : 0.0f;  // x*(0.5h+b)
            float dxa = xf - xa[m];
            float q1  = xdav - inner;
            tacc[m] = fmaf(dxa * dxa, 5e-5f, q1 * q1) - lpf - e1;
            if (ind) indmask |= (1u << m);
            unsigned pb = __ballot_sync(0xffffffffu, ind && xf == 0.0f);
            unsigned nb = __ballot_sync(0xffffffffu, ind && xf != 0.0f);
            if (lane == 0) { posw[m][warp] = pb; negw[m][warp] = nb; }
            xda[m] = xdav;
        }
        __syncthreads();

        // ---- stage 1b: expand bitmasks into per-row flip index lists ----
        // Order per row: chunk 0..7, within a chunk pos bits asc then neg bits asc
        // (identical accumulation order to the serial gather -> bit-identical h2).
        if (d < Mrows * NW) {
            int m = d >> 3, c = d & 7;
            int off = 0;
            #pragma unroll
            for (int c2 = 0; c2 < NW; c2++) {
                int cnt = __popc(posw[m][c2]) + __popc(negw[m][c2]);
                if (c2 < c) off += cnt;
            }
            int base = c * 32;
            unsigned pw = posw[m][c];
            while (pw) { int j = __ffs(pw) - 1; pw &= pw - 1; flist[m][off++] = (short)(base + j); }
            unsigned nw_ = negw[m][c];
            while (nw_) { int j = __ffs(nw_) - 1; nw_ &= nw_ - 1; flist[m][off++] = (short)(base + j + 256); }
            if (c == NW - 1) {
                int padded = (off + 7) & ~7;
                for (int i = off; i < padded; i++) flist[m][i] = (short)512;  // sign-0 pad
                fcnt[m] = padded;
            }
        }
        __syncthreads();

        // ---- stage 2: incremental h2 with 8-way batched loads, reverse terms ----
        #pragma unroll
        for (int m = 0; m < Mrows; m++) {
            float acc = h[m];
            const int cm = fcnt[m];
            for (int i = 0; i < cm; i += 8) {
                float wv[8], sv[8];
                #pragma unroll
                for (int j = 0; j < 8; j++) {
                    int v = (int)flist[m][i + j];
                    sv[j] = (v >= 512) ? 0.0f : ((v >= 256) ? -1.0f : 1.0f);
                    wv[j] = Wm[(v & 255) * Dm + d];   // 8 independent loads
                }
                #pragma unroll
                for (int j = 0; j < 8; j++) acc = fmaf(sv[j], wv[j], acc);
            }
            h2[m] = acc;

            float xf   = ((xmask >> m) & 1u) ? 1.0f : 0.0f;
            bool  ind  = (indmask >> m) & 1u;
            float xdv  = ind ? 1.0f - xf : xf;
            float sgn2 = 1.0f - 2.0f * xdv;
            float ga2  = (xdv - xda[m]) * 1e-4f;
            float hb2  = acc + bd;
            float gm2  = (hb2 * sgn2) * 0.5f - (ga2 * 0.5f) * sgn2;
            float fp2  = my_sigmoid(gm2 - 2.5f);
            float lpr  = my_log((ind ? fp2 : 1.0f - fp2) + 1e-10f);
            float e2   = (xdv != 0.0f) ? fmaf(0.5f, acc, bd) : 0.0f;
            float dxd  = xdv - xda[m];
            float inner2 = fmaf(0.25f, ga2, xda[m]);
            float q2   = xa[m] - inner2;
            float t = tacc[m] + lpr + e2 - fmaf(dxd * dxd, 5e-5f, q2 * q2);

            t += __shfl_down_sync(0xffffffffu, t, 16);
            t += __shfl_down_sync(0xffffffffu, t, 8);
            t += __shfl_down_sync(0xffffffffu, t, 4);
            t += __shfl_down_sync(0xffffffffu, t, 2);
            t += __shfl_down_sync(0xffffffffu, t, 1);
            if (lane == 0) red[m][warp] = t;
        }
        __syncthreads();

        // ---- MH accept per row ----
        if (d < Mrows) {
            float la = 0.0f;
            #pragma unroll
            for (int w2 = 0; w2 < NW; w2++) la += red[d][w2];
            float u = au[step * Bm + rowBase + d];
            float lu = (u > 0.0f) ? my_log(u) : -3.0e38f;
            accs[d] = (la > lu) ? 1.0f : 0.0f;
        }
        __syncthreads();

        // ---- commit ----
        #pragma unroll
        for (int m = 0; m < Mrows; m++) {
            if (accs[m] != 0.0f) {
                xa[m] = xda[m];
                h[m]  = h2[m];
                xmask ^= (indmask & (1u << m));
            }
        }
        __syncthreads();
    }

    #pragma unroll
    for (int m = 0; m < Mrows; m++) {
        float xf = ((xmask >> m) & 1u) ? 1.0f : 0.0f;
        out[(size_t)(rowBase + m) * Dm + d] = xf;
        out[(size_t)Bm * Dm + (size_t)(rowBase + m) * Dm + d] = xa[m];
    }
}

extern "C" void kernel_launch(void* const* d_in, const int* in_sizes, int n_in,
                              void* d_out, int out_size) {
    const float* x  = (const float*)d_in[0];
    const float* xa = (const float*)d_in[1];
    const float* W  = (const float*)d_in[2];
    const float* b  = (const float*)d_in[3];
    const float* rr = (const float*)d_in[4];
    const float* nz = (const float*)d_in[5];
    const float* au = (const float*)d_in[6];
    els_kernel<<<Bm / Mrows, 256>>>(x, xa, W, b, rr, nz, au, (float*)d_out);
}

// round 3
// speedup vs baseline: 2.5278x; 1.4813x over previous
#include <cuda_runtime.h>
#include <stdint.h>

#define Dm 256
#define Bm 16384
#define NSTEPS 5
#define Mrows 8
#define NW 8
#define LCAP 264   // max 256 flips + pad to multiple of 8

#define SIGNB 0x80000000
#define PADB  0x40000000
#define OFFM  0x0003FC00   // idx<<10 for idx<256

// ---- flag-independent accurate fp32 exp/log/sigmoid (pure FMA + __fdiv_rn) ----

static __device__ __forceinline__ float my_exp(float x) {
    x = fmaxf(x, -80.0f);
    float z = x * 1.4426950408889634f;
    float n = rintf(z);
    float r = fmaf(n, -0.693359375f, x);
    r = fmaf(n, 2.12194440054690583e-4f, r);
    float p = 1.9841269841269841e-4f;
    p = fmaf(p, r, 1.3888888888888889e-3f);
    p = fmaf(p, r, 8.3333333333333333e-3f);
    p = fmaf(p, r, 4.1666666666666664e-2f);
    p = fmaf(p, r, 1.6666666666666666e-1f);
    p = fmaf(p, r, 0.5f);
    p = fmaf(p, r, 1.0f);
    p = fmaf(p, r, 1.0f);
    int ni = (int)n;
    return p * __int_as_float((127 + ni) << 23);
}

static __device__ __forceinline__ float my_log(float v) {
    int i = __float_as_int(v);
    int e = (i - 0x3f3504f3) >> 23;
    float m = __int_as_float(i - (e << 23));
    float f = m - 1.0f;
    float s = __fdiv_rn(f, 2.0f + f);
    float s2 = s * s;
    float p = 0.22222222f;
    p = fmaf(p, s2, 0.28571429f);
    p = fmaf(p, s2, 0.4f);
    p = fmaf(p, s2, 0.66666667f);
    float logm = fmaf(p * s2, s, 2.0f * s);
    float ef = (float)e;
    return fmaf(ef, 0.693359375f, fmaf(ef, -2.12194440054690583e-4f, logm));
}

static __device__ __forceinline__ float my_sigmoid(float t) {
    float en = my_exp(-fabsf(t));
    float s = __fdiv_rn(en, 1.0f + en);
    return (t > 0.0f) ? 1.0f - s : s;
}

// ---- fused sampler: one block = 8 independent chains, thread d owns dim d ----

__global__ void __launch_bounds__(256, 3)
els_kernel(const float* __restrict__ x_in, const float* __restrict__ xa_in,
           const float* __restrict__ Wm, const float* __restrict__ bv,
           const float* __restrict__ rr, const float* __restrict__ noise,
           const float* __restrict__ au, float* __restrict__ out)
{
    const int d = threadIdx.x;
    const int warp = d >> 5;
    const int lane = d & 31;
    const int rowBase = blockIdx.x * Mrows;

    __shared__ float xs[Dm][Mrows];            // x as floats (init GEMM only)
    __shared__ unsigned posw[Mrows][NW];       // flip 0->1 bitmasks per 32-e chunk
    __shared__ unsigned negw[Mrows][NW];       // flip 1->0 bitmasks
    __shared__ int     flist[Mrows][LCAP];     // packed: signbit | (idx<<10); PADB = pad
    __shared__ int     fcnt[Mrows];            // exact (unpadded) list length
    __shared__ float   red[Mrows][NW];         // per-warp partial la
    __shared__ float   accs[Mrows];            // accept flags

    const float bd = bv[d];
    const char* wb = (const char*)(Wm + d);    // byte base for row gathers
    float xa[Mrows], h[Mrows];
    unsigned xmask = 0;

    #pragma unroll
    for (int m = 0; m < Mrows; m++) {
        float xv = __ldcs(&x_in[(size_t)(rowBase + m) * Dm + d]);
        xa[m] = __ldcs(&xa_in[(size_t)(rowBase + m) * Dm + d]);
        xs[d][m] = xv;
        if (xv != 0.0f) xmask |= (1u << m);
        h[m] = 0.0f;
    }
    __syncthreads();

    // init: h[m] = (x[m] @ W)[d]   rank-1 update sweep, x broadcast from smem
    #pragma unroll 4
    for (int e = 0; e < Dm; e++) {
        float w = Wm[e * Dm + d];
        const float4* xp = reinterpret_cast<const float4*>(xs[e]);
        float4 a0 = xp[0], a1 = xp[1];
        h[0] = fmaf(a0.x, w, h[0]);   h[1] = fmaf(a0.y, w, h[1]);
        h[2] = fmaf(a0.z, w, h[2]);   h[3] = fmaf(a0.w, w, h[3]);
        h[4] = fmaf(a1.x, w, h[4]);   h[5] = fmaf(a1.y, w, h[5]);
        h[6] = fmaf(a1.z, w, h[6]);   h[7] = fmaf(a1.w, w, h[7]);
    }

    for (int step = 0; step < NSTEPS; step++) {
        float xda[Mrows], h2[Mrows], tacc[Mrows];
        unsigned indmask = 0;

        // ---- stage 1: propose flips, forward log-prob terms ----
        #pragma unroll
        for (int m = 0; m < Mrows; m++) {
            float rv  = __ldcs(&rr[((size_t)(step * Bm + rowBase + m)) * Dm + d]);
            float nv  = __ldcs(&noise[((size_t)(step * Bm + rowBase + m)) * Dm + d]);
            float xf  = ((xmask >> m) & 1u) ? 1.0f : 0.0f;
            float sgn = 1.0f - 2.0f * xf;                    // -(2x-1)
            float ga  = (xf - xa[m]) * 1e-4f;                // (x - xa)/ETA
            float hb  = h[m] + bd;
            float gm  = (hb * sgn) * 0.5f - (ga * 0.5f) * sgn;
            float fp  = my_sigmoid(gm - 2.5f);
            bool ind  = rv < fp;
            float inner = xa[m] + 0.25f * ga;
            float pn  = __fmul_rn(0.70710678118654752f, nv);
            float xdav = inner + pn;
            float lpf = my_log((ind ? fp : 1.0f - fp) + 1e-10f);
            float e1  = (xf != 0.0f) ? fmaf(0.5f, h[m], bd) : 0.0f;  // x*(0.5h+b)
            float dxa = xf - xa[m];
            float q1  = xdav - inner;
            tacc[m] = fmaf(dxa * dxa, 5e-5f, q1 * q1) - lpf - e1;
            if (ind) indmask |= (1u << m);
            unsigned pb = __ballot_sync(0xffffffffu, ind && xf == 0.0f);
            unsigned nb = __ballot_sync(0xffffffffu, ind && xf != 0.0f);
            if (lane == 0) { posw[m][warp] = pb; negw[m][warp] = nb; }
            xda[m] = xdav;
        }
        __syncthreads();

        // ---- stage 1b: expand bitmasks into per-row packed flip lists ----
        // Order per row: chunk 0..7, within a chunk pos bits asc then neg bits asc
        // (identical accumulation order to serial gather -> bit-identical h2).
        if (d < Mrows * NW) {
            int m = d >> 3, c = d & 7;
            int off = 0;
            #pragma unroll
            for (int c2 = 0; c2 < NW; c2++) {
                int cnt = __popc(posw[m][c2]) + __popc(negw[m][c2]);
                if (c2 < c) off += cnt;
            }
            int base = c * 32;
            unsigned pw = posw[m][c];
            while (pw) { int j = __ffs(pw) - 1; pw &= pw - 1; flist[m][off++] = (base + j) << 10; }
            unsigned nw_ = negw[m][c];
            while (nw_) { int j = __ffs(nw_) - 1; nw_ &= nw_ - 1; flist[m][off++] = (int)(SIGNB | (unsigned)((base + j) << 10)); }
            if (c == NW - 1) {
                int padded = (off + 7) & ~7;
                for (int i = off; i < padded; i++) flist[m][i] = PADB;
                fcnt[m] = off;
            }
        }
        __syncthreads();

        // ---- stage 2: incremental h2, 8-way batched sign-XOR gather, reverse ----
        #pragma unroll
        for (int m = 0; m < Mrows; m++) {
            float acc = h[m];
            const int cm = fcnt[m];
            const int full = cm & ~7;
            for (int i = 0; i < full; i += 8) {
                int ev[8]; float wv[8];
                #pragma unroll
                for (int j = 0; j < 8; j++) ev[j] = flist[m][i + j];
                #pragma unroll
                for (int j = 0; j < 8; j++) {
                    float w = *reinterpret_cast<const float*>(wb + (ev[j] & OFFM));
                    wv[j] = __int_as_float(__float_as_int(w) ^ (ev[j] & SIGNB));
                }
                #pragma unroll
                for (int j = 0; j < 8; j++) acc += wv[j];
            }
            if (cm & 7) {   // one padded tail group: fmaf(sv in {+1,-1,0}) == exact
                #pragma unroll
                for (int j = 0; j < 8; j++) {
                    int e = flist[m][full + j];
                    float sv = (e & PADB) ? 0.0f : ((e < 0) ? -1.0f : 1.0f);
                    float w = *reinterpret_cast<const float*>(wb + (e & OFFM));
                    acc = fmaf(sv, w, acc);
                }
            }
            h2[m] = acc;

            float xf   = ((xmask >> m) & 1u) ? 1.0f : 0.0f;
            bool  ind  = (indmask >> m) & 1u;
            float xdv  = ind ? 1.0f - xf : xf;
            float sgn2 = 1.0f - 2.0f * xdv;
            float ga2  = (xdv - xda[m]) * 1e-4f;
            float hb2  = acc + bd;
            float gm2  = (hb2 * sgn2) * 0.5f - (ga2 * 0.5f) * sgn2;
            float fp2  = my_sigmoid(gm2 - 2.5f);
            float lpr  = my_log((ind ? fp2 : 1.0f - fp2) + 1e-10f);
            float e2   = (xdv != 0.0f) ? fmaf(0.5f, acc, bd) : 0.0f;
            float dxd  = xdv - xda[m];
            float inner2 = fmaf(0.25f, ga2, xda[m]);
            float q2   = xa[m] - inner2;
            float t = tacc[m] + lpr + e2 - fmaf(dxd * dxd, 5e-5f, q2 * q2);

            t += __shfl_down_sync(0xffffffffu, t, 16);
            t += __shfl_down_sync(0xffffffffu, t, 8);
            t += __shfl_down_sync(0xffffffffu, t, 4);
            t += __shfl_down_sync(0xffffffffu, t, 2);
            t += __shfl_down_sync(0xffffffffu, t, 1);
            if (lane == 0) red[m][warp] = t;
        }
        __syncthreads();

        // ---- MH accept per row ----
        if (d < Mrows) {
            float la = 0.0f;
            #pragma unroll
            for (int w2 = 0; w2 < NW; w2++) la += red[d][w2];
            float u = __ldcs(&au[step * Bm + rowBase + d]);
            float lu = (u > 0.0f) ? my_log(u) : -3.0e38f;
            accs[d] = (la > lu) ? 1.0f : 0.0f;
        }
        __syncthreads();

        // ---- commit ----
        #pragma unroll
        for (int m = 0; m < Mrows; m++) {
            if (accs[m] != 0.0f) {
                xa[m] = xda[m];
                h[m]  = h2[m];
                xmask ^= (indmask & (1u << m));
            }
        }
        __syncthreads();
    }

    #pragma unroll
    for (int m = 0; m < Mrows; m++) {
        float xf = ((xmask >> m) & 1u) ? 1.0f : 0.0f;
        __stcs(&out[(size_t)(rowBase + m) * Dm + d], xf);
        __stcs(&out[(size_t)Bm * Dm + (size_t)(rowBase + m) * Dm + d], xa[m]);
    }
}

extern "C" void kernel_launch(void* const* d_in, const int* in_sizes, int n_in,
                              void* d_out, int out_size) {
    const float* x  = (const float*)d_in[0];
    const float* xa = (const float*)d_in[1];
    const float* W  = (const float*)d_in[2];
    const float* b  = (const float*)d_in[3];
    const float* rr = (const float*)d_in[4];
    const float* nz = (const float*)d_in[5];
    const float* au = (const float*)d_in[6];
    els_kernel<<<Bm / Mrows, 256>>>(x, xa, W, b, rr, nz, au, (float*)d_out);
}

// round 4
// speedup vs baseline: 3.0836x; 1.2199x over previous
#include <cuda_runtime.h>
#include <stdint.h>

#define Dm 256
#define Bm 16384
#define NSTEPS 5
#define Mrows 8
#define NW 8
#define LCAP 264   // max 256 flips + pad to multiple of 8 (264*4 bytes, 16B-aligned rows)

#define SIGNB 0x80000000
#define PADB  0x40000000
#define OFFM  0x0003FC00   // idx<<10 (byte offset of W row) for idx<256

// ---- flag-independent fp32 exp/log/sigmoid (pure FMA; sigmoid keeps __fdiv_rn) ----

static __device__ __forceinline__ float my_exp(float x) {
    x = fmaxf(x, -80.0f);
    float z = x * 1.4426950408889634f;
    float n = rintf(z);
    float r = fmaf(n, -0.693359375f, x);
    r = fmaf(n, 2.12194440054690583e-4f, r);
    float p = 1.9841269841269841e-4f;
    p = fmaf(p, r, 1.3888888888888889e-3f);
    p = fmaf(p, r, 8.3333333333333333e-3f);
    p = fmaf(p, r, 4.1666666666666664e-2f);
    p = fmaf(p, r, 1.6666666666666666e-1f);
    p = fmaf(p, r, 0.5f);
    p = fmaf(p, r, 1.0f);
    p = fmaf(p, r, 1.0f);
    int ni = (int)n;
    return p * __int_as_float((127 + ni) << 23);
}

// division-free log (cephes-style); feeds only la (accept margin) -> ulp-level ok
static __device__ __forceinline__ float my_log(float v) {
    int i = __float_as_int(v);
    int e = (i - 0x3f3504f3) >> 23;
    float m = __int_as_float(i - (e << 23));   // m in [0.7071, 1.4142)
    float f = m - 1.0f;
    float z = f * f;
    float p = 7.0376836292e-2f;
    p = fmaf(p, f, -1.1514610310e-1f);
    p = fmaf(p, f, 1.1676998740e-1f);
    p = fmaf(p, f, -1.2420140846e-1f);
    p = fmaf(p, f, 1.4249322787e-1f);
    p = fmaf(p, f, -1.6668057665e-1f);
    p = fmaf(p, f, 2.0000714765e-1f);
    p = fmaf(p, f, -2.4999993993e-1f);
    p = fmaf(p, f, 3.3333331174e-1f);
    float r = fmaf(p * z, f, fmaf(-0.5f, z, f));
    float ef = (float)e;
    return fmaf(ef, 0.693359375f, fmaf(ef, -2.12194440054690583e-4f, r));
}

static __device__ __forceinline__ float my_sigmoid(float t) {   // decision-critical: unchanged
    float en = my_exp(-fabsf(t));
    float s = __fdiv_rn(en, 1.0f + en);
    return (t > 0.0f) ? 1.0f - s : s;
}

// ---- fused sampler: one block = 8 independent chains, thread d owns dim d ----

__global__ void __launch_bounds__(256, 4)
els_kernel(const float* __restrict__ x_in, const float* __restrict__ xa_in,
           const float* __restrict__ Wm, const float* __restrict__ bv,
           const float* __restrict__ rr, const float* __restrict__ noise,
           const float* __restrict__ au, float* __restrict__ out)
{
    const int d = threadIdx.x;
    const int warp = d >> 5;
    const int lane = d & 31;
    const int rowBase = blockIdx.x * Mrows;

    __shared__ float xs[Dm][Mrows];            // x as floats (init GEMM only)
    __shared__ unsigned posw[Mrows][NW];
    __shared__ unsigned negw[Mrows][NW];
    __shared__ int     flist[Mrows][LCAP];     // packed: signbit | (idx<<10); PADB = pad
    __shared__ int     fcnt[Mrows];
    __shared__ float   red[Mrows][NW];
    __shared__ float   accs[Mrows];
    __shared__ float   xdas[Mrows][Dm];        // proposal xa  (was registers)
    __shared__ float   taccs[Mrows][Dm];       // fwd partial  (was registers)
    __shared__ float   h2s[Mrows][Dm];         // proposal h   (was registers)

    const float bd = bv[d];
    const char* wb = (const char*)(Wm + d);    // byte base for row gathers
    float xa[Mrows], h[Mrows];
    unsigned xmask = 0;

    #pragma unroll
    for (int m = 0; m < Mrows; m++) {
        float xv = __ldcs(&x_in[(size_t)(rowBase + m) * Dm + d]);
        xa[m] = __ldcs(&xa_in[(size_t)(rowBase + m) * Dm + d]);
        xs[d][m] = xv;
        if (xv != 0.0f) xmask |= (1u << m);
        h[m] = 0.0f;
    }
    __syncthreads();

    // init: h[m] = (x[m] @ W)[d]  — order preserved exactly (decision-critical)
    #pragma unroll 4
    for (int e = 0; e < Dm; e++) {
        float w = Wm[e * Dm + d];
        const float4* xp = reinterpret_cast<const float4*>(xs[e]);
        float4 a0 = xp[0], a1 = xp[1];
        h[0] = fmaf(a0.x, w, h[0]);   h[1] = fmaf(a0.y, w, h[1]);
        h[2] = fmaf(a0.z, w, h[2]);   h[3] = fmaf(a0.w, w, h[3]);
        h[4] = fmaf(a1.x, w, h[4]);   h[5] = fmaf(a1.y, w, h[5]);
        h[6] = fmaf(a1.z, w, h[6]);   h[7] = fmaf(a1.w, w, h[7]);
    }

    for (int step = 0; step < NSTEPS; step++) {
        unsigned indmask = 0;

        // ---- stage 1: propose flips, forward log-prob terms ----
        #pragma unroll
        for (int m = 0; m < Mrows; m++) {
            float rv  = __ldcs(&rr[((size_t)(step * Bm + rowBase + m)) * Dm + d]);
            float nv  = __ldcs(&noise[((size_t)(step * Bm + rowBase + m)) * Dm + d]);
            float xf  = ((xmask >> m) & 1u) ? 1.0f : 0.0f;
            float sgn = 1.0f - 2.0f * xf;                    // -(2x-1)
            float ga  = (xf - xa[m]) * 1e-4f;                // (x - xa)/ETA
            float hb  = h[m] + bd;
            float gm  = (hb * sgn) * 0.5f - (ga * 0.5f) * sgn;
            float fp  = my_sigmoid(gm - 2.5f);
            bool ind  = rv < fp;
            float inner = xa[m] + 0.25f * ga;
            float pn  = __fmul_rn(0.70710678118654752f, nv);
            float xdav = inner + pn;
            float lpf = my_log((ind ? fp : 1.0f - fp) + 1e-10f);
            float e1  = (xf != 0.0f) ? fmaf(0.5f, h[m], bd) : 0.0f;  // x*(0.5h+b)
            float dxa = xf - xa[m];
            float q1  = xdav - inner;
            taccs[m][d] = fmaf(dxa * dxa, 5e-5f, q1 * q1) - lpf - e1;
            if (ind) indmask |= (1u << m);
            unsigned pb = __ballot_sync(0xffffffffu, ind && xf == 0.0f);
            unsigned nb = __ballot_sync(0xffffffffu, ind && xf != 0.0f);
            if (lane == 0) { posw[m][warp] = pb; negw[m][warp] = nb; }
            xdas[m][d] = xdav;
        }
        __syncthreads();

        // ---- stage 1b: expand bitmasks into per-row packed flip lists ----
        // Order: chunk 0..7, pos asc then neg asc per chunk (bit-identical h2 order).
        if (d < Mrows * NW) {
            int m = d >> 3, c = d & 7;
            int off = 0;
            #pragma unroll
            for (int c2 = 0; c2 < NW; c2++) {
                int cnt = __popc(posw[m][c2]) + __popc(negw[m][c2]);
                if (c2 < c) off += cnt;
            }
            int base = c * 32;
            unsigned pw = posw[m][c];
            while (pw) { int j = __ffs(pw) - 1; pw &= pw - 1; flist[m][off++] = (base + j) << 10; }
            unsigned nw_ = negw[m][c];
            while (nw_) { int j = __ffs(nw_) - 1; nw_ &= nw_ - 1; flist[m][off++] = (int)(SIGNB | (unsigned)((base + j) << 10)); }
            if (c == NW - 1) {
                int padded = (off + 7) & ~7;
                for (int i = off; i < padded; i++) flist[m][i] = PADB;
                fcnt[m] = off;
            }
        }
        __syncthreads();

        // ---- stage 2: incremental h2 (8-way batched sign-XOR gather), reverse terms ----
        #pragma unroll
        for (int m = 0; m < Mrows; m++) {
            float acc = h[m];
            const int cm = fcnt[m];
            const int full = cm & ~7;
            const int4* fl4 = reinterpret_cast<const int4*>(flist[m]);
            for (int i = 0; i < full; i += 8) {
                int4 ea = fl4[i >> 2];
                int4 eb = fl4[(i >> 2) + 1];
                float wv[8];
                wv[0] = *reinterpret_cast<const float*>(wb + (ea.x & OFFM));
                wv[1] = *reinterpret_cast<const float*>(wb + (ea.y & OFFM));
                wv[2] = *reinterpret_cast<const float*>(wb + (ea.z & OFFM));
                wv[3] = *reinterpret_cast<const float*>(wb + (ea.w & OFFM));
                wv[4] = *reinterpret_cast<const float*>(wb + (eb.x & OFFM));
                wv[5] = *reinterpret_cast<const float*>(wb + (eb.y & OFFM));
                wv[6] = *reinterpret_cast<const float*>(wb + (eb.z & OFFM));
                wv[7] = *reinterpret_cast<const float*>(wb + (eb.w & OFFM));
                acc += __int_as_float(__float_as_int(wv[0]) ^ (ea.x & SIGNB));
                acc += __int_as_float(__float_as_int(wv[1]) ^ (ea.y & SIGNB));
                acc += __int_as_float(__float_as_int(wv[2]) ^ (ea.z & SIGNB));
                acc += __int_as_float(__float_as_int(wv[3]) ^ (ea.w & SIGNB));
                acc += __int_as_float(__float_as_int(wv[4]) ^ (eb.x & SIGNB));
                acc += __int_as_float(__float_as_int(wv[5]) ^ (eb.y & SIGNB));
                acc += __int_as_float(__float_as_int(wv[6]) ^ (eb.z & SIGNB));
                acc += __int_as_float(__float_as_int(wv[7]) ^ (eb.w & SIGNB));
            }
            if (cm & 7) {   // one padded tail group: fmaf(sv in {+1,-1,0}) rounds identically
                int4 ea = fl4[full >> 2];
                int4 eb = fl4[(full >> 2) + 1];
                int ev[8] = {ea.x, ea.y, ea.z, ea.w, eb.x, eb.y, eb.z, eb.w};
                #pragma unroll
                for (int j = 0; j < 8; j++) {
                    int e = ev[j];
                    float sv = (e & PADB) ? 0.0f : ((e < 0) ? -1.0f : 1.0f);
                    float w = *reinterpret_cast<const float*>(wb + (e & OFFM));
                    acc = fmaf(sv, w, acc);
                }
            }
            h2s[m][d] = acc;

            float xdav = xdas[m][d];
            float xf   = ((xmask >> m) & 1u) ? 1.0f : 0.0f;
            bool  ind  = (indmask >> m) & 1u;
            float xdv  = ind ? 1.0f - xf : xf;
            float sgn2 = 1.0f - 2.0f * xdv;
            float ga2  = (xdv - xdav) * 1e-4f;
            float hb2  = acc + bd;
            float gm2  = (hb2 * sgn2) * 0.5f - (ga2 * 0.5f) * sgn2;
            float fp2  = my_sigmoid(gm2 - 2.5f);
            float lpr  = my_log((ind ? fp2 : 1.0f - fp2) + 1e-10f);
            float e2   = (xdv != 0.0f) ? fmaf(0.5f, acc, bd) : 0.0f;
            float dxd  = xdv - xdav;
            float inner2 = fmaf(0.25f, ga2, xdav);
            float q2   = xa[m] - inner2;
            float t = taccs[m][d] + lpr + e2 - fmaf(dxd * dxd, 5e-5f, q2 * q2);

            t += __shfl_down_sync(0xffffffffu, t, 16);
            t += __shfl_down_sync(0xffffffffu, t, 8);
            t += __shfl_down_sync(0xffffffffu, t, 4);
            t += __shfl_down_sync(0xffffffffu, t, 2);
            t += __shfl_down_sync(0xffffffffu, t, 1);
            if (lane == 0) red[m][warp] = t;
        }
        __syncthreads();

        // ---- MH accept per row ----
        if (d < Mrows) {
            float la = 0.0f;
            #pragma unroll
            for (int w2 = 0; w2 < NW; w2++) la += red[d][w2];
            float u = __ldcs(&au[step * Bm + rowBase + d]);
            float lu = (u > 0.0f) ? my_log(u) : -3.0e38f;
            accs[d] = (la > lu) ? 1.0f : 0.0f;
        }
        __syncthreads();

        // ---- commit ----
        #pragma unroll
        for (int m = 0; m < Mrows; m++) {
            if (accs[m] != 0.0f) {
                xa[m] = xdas[m][d];
                h[m]  = h2s[m][d];
                xmask ^= (indmask & (1u << m));
            }
        }
        __syncthreads();
    }

    #pragma unroll
    for (int m = 0; m < Mrows; m++) {
        float xf = ((xmask >> m) & 1u) ? 1.0f : 0.0f;
        __stcs(&out[(size_t)(rowBase + m) * Dm + d], xf);
        __stcs(&out[(size_t)Bm * Dm + (size_t)(rowBase + m) * Dm + d], xa[m]);
    }
}

extern "C" void kernel_launch(void* const* d_in, const int* in_sizes, int n_in,
                              void* d_out, int out_size) {
    const float* x  = (const float*)d_in[0];
    const float* xa = (const float*)d_in[1];
    const float* W  = (const float*)d_in[2];
    const float* b  = (const float*)d_in[3];
    const float* rr = (const float*)d_in[4];
    const float* nz = (const float*)d_in[5];
    const float* au = (const float*)d_in[6];
    els_kernel<<<Bm / Mrows, 256>>>(x, xa, W, b, rr, nz, au, (float*)d_out);
}

// round 5
// speedup vs baseline: 3.6293x; 1.1770x over previous
#include <cuda_runtime.h>
#include <stdint.h>

#define Dm 256
#define Bm 16384
#define NSTEPS 5
#define Mrows 8
#define NW 8
#define LCAP 264

#define SIGNB 0x80000000
#define PADB  0x40000000
#define OFFM  0x0003FC00   // idx<<10 (byte offset of W row) for idx<256

// ---- flag-independent fp32 exp/log/sigmoid (pure FMA; sigmoid keeps __fdiv_rn) ----

static __device__ __forceinline__ float my_exp(float x) {
    x = fmaxf(x, -80.0f);
    float z = x * 1.4426950408889634f;
    float n = rintf(z);
    float r = fmaf(n, -0.693359375f, x);
    r = fmaf(n, 2.12194440054690583e-4f, r);
    float p = 1.9841269841269841e-4f;
    p = fmaf(p, r, 1.3888888888888889e-3f);
    p = fmaf(p, r, 8.3333333333333333e-3f);
    p = fmaf(p, r, 4.1666666666666664e-2f);
    p = fmaf(p, r, 1.6666666666666666e-1f);
    p = fmaf(p, r, 0.5f);
    p = fmaf(p, r, 1.0f);
    p = fmaf(p, r, 1.0f);
    int ni = (int)n;
    return p * __int_as_float((127 + ni) << 23);
}

static __device__ __forceinline__ float my_log(float v) {
    int i = __float_as_int(v);
    int e = (i - 0x3f3504f3) >> 23;
    float m = __int_as_float(i - (e << 23));
    float f = m - 1.0f;
    float z = f * f;
    float p = 7.0376836292e-2f;
    p = fmaf(p, f, -1.1514610310e-1f);
    p = fmaf(p, f, 1.1676998740e-1f);
    p = fmaf(p, f, -1.2420140846e-1f);
    p = fmaf(p, f, 1.4249322787e-1f);
    p = fmaf(p, f, -1.6668057665e-1f);
    p = fmaf(p, f, 2.0000714765e-1f);
    p = fmaf(p, f, -2.4999993993e-1f);
    p = fmaf(p, f, 3.3333331174e-1f);
    float r = fmaf(p * z, f, fmaf(-0.5f, z, f));
    float ef = (float)e;
    return fmaf(ef, 0.693359375f, fmaf(ef, -2.12194440054690583e-4f, r));
}

static __device__ __forceinline__ float my_sigmoid(float t) {   // decision-critical: unchanged
    float en = my_exp(-fabsf(t));
    float s = __fdiv_rn(en, 1.0f + en);
    return (t > 0.0f) ? 1.0f - s : s;
}

static __device__ __forceinline__ float sxor(float w, int e) {  // w * sign(e) via bit xor
    return __int_as_float(__float_as_int(w) ^ (e & SIGNB));
}

// ---- fused sampler: one block = 8 chains; thread d owns dim d for math,
// ---- gather phase re-maps to (64 dim-quads x 4 row-pairs) with LDG.128 ----

__global__ void __launch_bounds__(256, 4)
els_kernel(const float* __restrict__ x_in, const float* __restrict__ xa_in,
           const float* __restrict__ Wm, const float* __restrict__ bv,
           const float* __restrict__ rr, const float* __restrict__ noise,
           const float* __restrict__ au, float* __restrict__ out)
{
    const int d = threadIdx.x;
    const int warp = d >> 5;
    const int lane = d & 31;
    const int rowBase = blockIdx.x * Mrows;

    __shared__ float   xh[Dm * Mrows];         // init: xs[e*8+m]; after: hs[m*256+d]
    __shared__ unsigned posw[Mrows][NW];
    __shared__ unsigned negw[Mrows][NW];
    __shared__ int     flist[Mrows][LCAP];     // packed: signbit | (idx<<10); PADB = pad
    __shared__ int     fcnt[Mrows];            // exact count
    __shared__ float   red[Mrows][NW];
    __shared__ float   accs[Mrows];
    __shared__ float   xdas[Mrows][Dm];
    __shared__ float   taccs[Mrows][Dm];
    __shared__ float   h2s[Mrows][Dm];

    const float bd = bv[d];
    float xa[Mrows], h[Mrows];
    unsigned xmask = 0;

    #pragma unroll
    for (int m = 0; m < Mrows; m++) {
        float xv = __ldcs(&x_in[(size_t)(rowBase + m) * Dm + d]);
        xa[m] = __ldcs(&xa_in[(size_t)(rowBase + m) * Dm + d]);
        xh[d * Mrows + m] = xv;
        if (xv != 0.0f) xmask |= (1u << m);
        h[m] = 0.0f;
    }
    __syncthreads();

    // init: h[m] = (x[m] @ W)[d]  — order preserved exactly (decision-critical)
    #pragma unroll 4
    for (int e = 0; e < Dm; e++) {
        float w = Wm[e * Dm + d];
        const float4* xp = reinterpret_cast<const float4*>(&xh[e * Mrows]);
        float4 a0 = xp[0], a1 = xp[1];
        h[0] = fmaf(a0.x, w, h[0]);   h[1] = fmaf(a0.y, w, h[1]);
        h[2] = fmaf(a0.z, w, h[2]);   h[3] = fmaf(a0.w, w, h[3]);
        h[4] = fmaf(a1.x, w, h[4]);   h[5] = fmaf(a1.y, w, h[5]);
        h[6] = fmaf(a1.z, w, h[6]);   h[7] = fmaf(a1.w, w, h[7]);
    }
    __syncthreads();                            // all xs reads done; re-purpose as hs
    #pragma unroll
    for (int m = 0; m < Mrows; m++) xh[m * Dm + d] = h[m];

    for (int step = 0; step < NSTEPS; step++) {
        unsigned indmask = 0;

        // ---- stage 1: propose flips, forward log-prob terms ----
        #pragma unroll
        for (int m = 0; m < Mrows; m++) {
            float rv  = __ldcs(&rr[((size_t)(step * Bm + rowBase + m)) * Dm + d]);
            float nv  = __ldcs(&noise[((size_t)(step * Bm + rowBase + m)) * Dm + d]);
            float hm  = xh[m * Dm + d];
            float xf  = ((xmask >> m) & 1u) ? 1.0f : 0.0f;
            float sgn = 1.0f - 2.0f * xf;                    // -(2x-1)
            float ga  = (xf - xa[m]) * 1e-4f;                // (x - xa)/ETA
            float hb  = hm + bd;
            float gm  = (hb * sgn) * 0.5f - (ga * 0.5f) * sgn;
            float fp  = my_sigmoid(gm - 2.5f);
            bool ind  = rv < fp;
            float inner = xa[m] + 0.25f * ga;
            float pn  = __fmul_rn(0.70710678118654752f, nv);
            float xdav = inner + pn;
            float lpf = my_log((ind ? fp : 1.0f - fp) + 1e-10f);
            float e1  = (xf != 0.0f) ? fmaf(0.5f, hm, bd) : 0.0f;  // x*(0.5h+b)
            float dxa = xf - xa[m];
            float q1  = xdav - inner;
            taccs[m][d] = fmaf(dxa * dxa, 5e-5f, q1 * q1) - lpf - e1;
            if (ind) indmask |= (1u << m);
            unsigned pb = __ballot_sync(0xffffffffu, ind && xf == 0.0f);
            unsigned nb = __ballot_sync(0xffffffffu, ind && xf != 0.0f);
            if (lane == 0) { posw[m][warp] = pb; negw[m][warp] = nb; }
            xdas[m][d] = xdav;
        }
        __syncthreads();

        // ---- stage 1b: expand bitmasks into per-row packed flip lists ----
        // Order: chunk 0..7, pos asc then neg asc per chunk (bit-identical h2 order).
        if (d < Mrows * NW) {
            int m = d >> 3, c = d & 7;
            int off = 0;
            #pragma unroll
            for (int c2 = 0; c2 < NW; c2++) {
                int cnt = __popc(posw[m][c2]) + __popc(negw[m][c2]);
                if (c2 < c) off += cnt;
            }
            int base = c * 32;
            unsigned pw = posw[m][c];
            while (pw) { int j = __ffs(pw) - 1; pw &= pw - 1; flist[m][off++] = (base + j) << 10; }
            unsigned nw_ = negw[m][c];
            while (nw_) { int j = __ffs(nw_) - 1; nw_ &= nw_ - 1; flist[m][off++] = (int)(SIGNB | (unsigned)((base + j) << 10)); }
            if (c == NW - 1) {
                int padded = (off + 3) & ~3;
                for (int i = off; i < padded; i++) flist[m][i] = PADB;
                fcnt[m] = off;
            }
        }
        __syncthreads();

        // ---- stage 2a: float4 gather — thread = (dim quad g, row pair rp) ----
        {
            const int g  = d & 63;
            const int rp = d >> 6;
            const char* wbase = (const char*)Wm + g * 16;
            #pragma unroll
            for (int t = 0; t < 2; t++) {
                const int m = rp + t * 4;
                const int cnt  = fcnt[m];
                const int full = cnt & ~3;
                const int* fl = flist[m];
                float4 acc = *reinterpret_cast<const float4*>(&xh[m * Dm + g * 4]);
                for (int i = 0; i < full; i += 4) {
                    int e0 = fl[i], e1 = fl[i + 1], e2 = fl[i + 2], e3 = fl[i + 3];
                    float4 w0 = *reinterpret_cast<const float4*>(wbase + (e0 & OFFM));
                    float4 w1 = *reinterpret_cast<const float4*>(wbase + (e1 & OFFM));
                    float4 w2 = *reinterpret_cast<const float4*>(wbase + (e2 & OFFM));
                    float4 w3 = *reinterpret_cast<const float4*>(wbase + (e3 & OFFM));
                    acc.x += sxor(w0.x, e0); acc.y += sxor(w0.y, e0);
                    acc.z += sxor(w0.z, e0); acc.w += sxor(w0.w, e0);
                    acc.x += sxor(w1.x, e1); acc.y += sxor(w1.y, e1);
                    acc.z += sxor(w1.z, e1); acc.w += sxor(w1.w, e1);
                    acc.x += sxor(w2.x, e2); acc.y += sxor(w2.y, e2);
                    acc.z += sxor(w2.z, e2); acc.w += sxor(w2.w, e2);
                    acc.x += sxor(w3.x, e3); acc.y += sxor(w3.y, e3);
                    acc.z += sxor(w3.z, e3); acc.w += sxor(w3.w, e3);
                }
                if (cnt & 3) {   // one padded tail group: fmaf(sv in {+1,-1,0}) exact
                    #pragma unroll
                    for (int j = 0; j < 4; j++) {
                        int e = fl[full + j];
                        float sv = (e & PADB) ? 0.0f : ((e < 0) ? -1.0f : 1.0f);
                        float4 w = *reinterpret_cast<const float4*>(wbase + (e & OFFM));
                        acc.x = fmaf(sv, w.x, acc.x);
                        acc.y = fmaf(sv, w.y, acc.y);
                        acc.z = fmaf(sv, w.z, acc.z);
                        acc.w = fmaf(sv, w.w, acc.w);
                    }
                }
                *reinterpret_cast<float4*>(&h2s[m][g * 4]) = acc;
            }
        }
        __syncthreads();

        // ---- stage 2b: reverse terms + per-row la reduce (owner thread d) ----
        #pragma unroll
        for (int m = 0; m < Mrows; m++) {
            float acc  = h2s[m][d];
            float xdav = xdas[m][d];
            float xf   = ((xmask >> m) & 1u) ? 1.0f : 0.0f;
            bool  ind  = (indmask >> m) & 1u;
            float xdv  = ind ? 1.0f - xf : xf;
            float sgn2 = 1.0f - 2.0f * xdv;
            float ga2  = (xdv - xdav) * 1e-4f;
            float hb2  = acc + bd;
            float gm2  = (hb2 * sgn2) * 0.5f - (ga2 * 0.5f) * sgn2;
            float fp2  = my_sigmoid(gm2 - 2.5f);
            float lpr  = my_log((ind ? fp2 : 1.0f - fp2) + 1e-10f);
            float e2   = (xdv != 0.0f) ? fmaf(0.5f, acc, bd) : 0.0f;
            float dxd  = xdv - xdav;
            float inner2 = fmaf(0.25f, ga2, xdav);
            float q2   = xa[m] - inner2;
            float t = taccs[m][d] + lpr + e2 - fmaf(dxd * dxd, 5e-5f, q2 * q2);

            t += __shfl_down_sync(0xffffffffu, t, 16);
            t += __shfl_down_sync(0xffffffffu, t, 8);
            t += __shfl_down_sync(0xffffffffu, t, 4);
            t += __shfl_down_sync(0xffffffffu, t, 2);
            t += __shfl_down_sync(0xffffffffu, t, 1);
            if (lane == 0) red[m][warp] = t;
        }
        __syncthreads();

        // ---- MH accept per row ----
        if (d < Mrows) {
            float la = 0.0f;
            #pragma unroll
            for (int w2 = 0; w2 < NW; w2++) la += red[d][w2];
            float u = __ldcs(&au[step * Bm + rowBase + d]);
            float lu = (u > 0.0f) ? my_log(u) : -3.0e38f;
            accs[d] = (la > lu) ? 1.0f : 0.0f;
        }
        __syncthreads();

        // ---- commit ----
        #pragma unroll
        for (int m = 0; m < Mrows; m++) {
            if (accs[m] != 0.0f) {
                xa[m] = xdas[m][d];
                xh[m * Dm + d] = h2s[m][d];
                xmask ^= (indmask & (1u << m));
            }
        }
        __syncthreads();
    }

    #pragma unroll
    for (int m = 0; m < Mrows; m++) {
        float xf = ((xmask >> m) & 1u) ? 1.0f : 0.0f;
        __stcs(&out[(size_t)(rowBase + m) * Dm + d], xf);
        __stcs(&out[(size_t)Bm * Dm + (size_t)(rowBase + m) * Dm + d], xa[m]);
    }
}

extern "C" void kernel_launch(void* const* d_in, const int* in_sizes, int n_in,
                              void* d_out, int out_size) {
    const float* x  = (const float*)d_in[0];
    const float* xa = (const float*)d_in[1];
    const float* W  = (const float*)d_in[2];
    const float* b  = (const float*)d_in[3];
    const float* rr = (const float*)d_in[4];
    const float* nz = (const float*)d_in[5];
    const float* au = (const float*)d_in[6];
    els_kernel<<<Bm / Mrows, 256>>>(x, xa, W, b, rr, nz, au, (float*)d_out);
}

// round 6
// speedup vs baseline: 3.8353x; 1.0568x over previous
#include <cuda_runtime.h>
#include <stdint.h>

#define Dm 256
#define Bm 16384
#define NSTEPS 5
#define Mrows 8
#define NW 8
#define LCAP 264

#define SIGNB 0x80000000
#define PADB  0x40000000
#define OFFM  0x0003FC00   // idx<<10 (byte offset of W row) for idx<256

// ---- flag-independent fp32 exp/log/sigmoid (pure FMA; sigmoid keeps __fdiv_rn) ----

static __device__ __forceinline__ float my_exp(float x) {
    x = fmaxf(x, -80.0f);
    float z = x * 1.4426950408889634f;
    float n = rintf(z);
    float r = fmaf(n, -0.693359375f, x);
    r = fmaf(n, 2.12194440054690583e-4f, r);
    float p = 1.9841269841269841e-4f;
    p = fmaf(p, r, 1.3888888888888889e-3f);
    p = fmaf(p, r, 8.3333333333333333e-3f);
    p = fmaf(p, r, 4.1666666666666664e-2f);
    p = fmaf(p, r, 1.6666666666666666e-1f);
    p = fmaf(p, r, 0.5f);
    p = fmaf(p, r, 1.0f);
    p = fmaf(p, r, 1.0f);
    int ni = (int)n;
    return p * __int_as_float((127 + ni) << 23);
}

static __device__ __forceinline__ float my_log(float v) {
    int i = __float_as_int(v);
    int e = (i - 0x3f3504f3) >> 23;
    float m = __int_as_float(i - (e << 23));
    float f = m - 1.0f;
    float z = f * f;
    float p = 7.0376836292e-2f;
    p = fmaf(p, f, -1.1514610310e-1f);
    p = fmaf(p, f, 1.1676998740e-1f);
    p = fmaf(p, f, -1.2420140846e-1f);
    p = fmaf(p, f, 1.4249322787e-1f);
    p = fmaf(p, f, -1.6668057665e-1f);
    p = fmaf(p, f, 2.0000714765e-1f);
    p = fmaf(p, f, -2.4999993993e-1f);
    p = fmaf(p, f, 3.3333331174e-1f);
    float r = fmaf(p * z, f, fmaf(-0.5f, z, f));
    float ef = (float)e;
    return fmaf(ef, 0.693359375f, fmaf(ef, -2.12194440054690583e-4f, r));
}

static __device__ __forceinline__ float my_sigmoid(float t) {   // decision-critical: unchanged
    float en = my_exp(-fabsf(t));
    float s = __fdiv_rn(en, 1.0f + en);
    return (t > 0.0f) ? 1.0f - s : s;
}

static __device__ __forceinline__ float sxor(float w, int e) {  // w * sign(e) via bit xor
    return __int_as_float(__float_as_int(w) ^ (e & SIGNB));
}

// ---- fused sampler: one block = 8 chains; thread d owns dim d for math,
// ---- gathers re-map to (64 dim-quads x 4 row-pairs) with LDG.128 ----

__global__ void __launch_bounds__(256, 4)
els_kernel(const float* __restrict__ x_in, const float* __restrict__ xa_in,
           const float* __restrict__ Wm, const float* __restrict__ bv,
           const float* __restrict__ rr, const float* __restrict__ noise,
           const float* __restrict__ au, float* __restrict__ out)
{
    const int d = threadIdx.x;
    const int warp = d >> 5;
    const int lane = d & 31;
    const int rowBase = blockIdx.x * Mrows;

    __shared__ float   xh[Mrows * Dm];         // h state, [m*256 + d]
    __shared__ unsigned posw[Mrows][NW];
    __shared__ unsigned negw[Mrows][NW];
    __shared__ int     flist[Mrows][LCAP];     // packed: signbit | (idx<<10); PADB = pad
    __shared__ int     fcnt[Mrows];
    __shared__ float   red[Mrows][NW];
    __shared__ float   accs[Mrows];
    __shared__ float   xdas[Mrows][Dm];
    __shared__ float   taccs[Mrows][Dm];
    __shared__ float   h2s[Mrows][Dm];

    const float bd = bv[d];
    float xa[Mrows];
    unsigned xmask = 0;

    // ---- load x/xa; ballot x-bits into posw (init "flip list" = ones of x) ----
    #pragma unroll
    for (int m = 0; m < Mrows; m++) {
        float xv = __ldcs(&x_in[(size_t)(rowBase + m) * Dm + d]);
        xa[m] = __ldcs(&xa_in[(size_t)(rowBase + m) * Dm + d]);
        bool one = xv != 0.0f;
        if (one) xmask |= (1u << m);
        unsigned pb = __ballot_sync(0xffffffffu, one);
        if (lane == 0) { posw[m][warp] = pb; negw[m][warp] = 0u; }
    }
    // prefetch step-0 rr/noise lines into L2 while init runs
    if (lane == 0) {
        size_t base0 = (size_t)rowBase * Dm + (warp << 5);
        #pragma unroll
        for (int m = 0; m < Mrows; m++) {
            asm volatile("prefetch.global.L2 [%0];" :: "l"(rr + base0 + (size_t)m * Dm));
            asm volatile("prefetch.global.L2 [%0];" :: "l"(noise + base0 + (size_t)m * Dm));
        }
    }
    __syncthreads();

    // ---- expand x-bit masks into ascending-e lists (sign-free) ----
    if (d < Mrows * NW) {
        int m = d >> 3, c = d & 7;
        int off = 0;
        #pragma unroll
        for (int c2 = 0; c2 < NW; c2++) {
            int cnt = __popc(posw[m][c2]);
            if (c2 < c) off += cnt;
        }
        int base = c * 32;
        unsigned pw = posw[m][c];
        while (pw) { int j = __ffs(pw) - 1; pw &= pw - 1; flist[m][off++] = (base + j) << 10; }
        if (c == NW - 1) {
            int padded = (off + 3) & ~3;
            for (int i = off; i < padded; i++) flist[m][i] = PADB;
            fcnt[m] = off;
        }
    }
    __syncthreads();

    // ---- init gather: h[m][d] = sum_{e: x=1} W[e][d]  (== FMA loop skipping
    // ---- exact zeros, ascending e => bit-identical to the dense matvec) ----
    {
        const int g  = d & 63;
        const int rp = d >> 6;
        const char* wbase = (const char*)Wm + g * 16;
        #pragma unroll
        for (int t = 0; t < 2; t++) {
            const int m = rp + t * 4;
            const int cnt  = fcnt[m];
            const int full = cnt & ~3;
            const int* fl = flist[m];
            const int4* fl4 = reinterpret_cast<const int4*>(fl);
            float4 acc = make_float4(0.0f, 0.0f, 0.0f, 0.0f);
            int4 en = fl4[0];
            for (int i = 0; i < full; i += 4) {
                int4 e = en;
                en = fl4[(i >> 2) + 1];
                float4 w0 = *reinterpret_cast<const float4*>(wbase + (e.x & OFFM));
                float4 w1 = *reinterpret_cast<const float4*>(wbase + (e.y & OFFM));
                float4 w2 = *reinterpret_cast<const float4*>(wbase + (e.z & OFFM));
                float4 w3 = *reinterpret_cast<const float4*>(wbase + (e.w & OFFM));
                acc.x += w0.x; acc.y += w0.y; acc.z += w0.z; acc.w += w0.w;
                acc.x += w1.x; acc.y += w1.y; acc.z += w1.z; acc.w += w1.w;
                acc.x += w2.x; acc.y += w2.y; acc.z += w2.z; acc.w += w2.w;
                acc.x += w3.x; acc.y += w3.y; acc.z += w3.z; acc.w += w3.w;
            }
            if (cnt & 3) {
                #pragma unroll
                for (int j = 0; j < 4; j++) {
                    int e = fl[full + j];
                    float sv = (e & PADB) ? 0.0f : 1.0f;
                    float4 w = *reinterpret_cast<const float4*>(wbase + (e & OFFM));
                    acc.x = fmaf(sv, w.x, acc.x);
                    acc.y = fmaf(sv, w.y, acc.y);
                    acc.z = fmaf(sv, w.z, acc.z);
                    acc.w = fmaf(sv, w.w, acc.w);
                }
            }
            *reinterpret_cast<float4*>(&xh[m * Dm + g * 4]) = acc;
        }
    }
    __syncthreads();

    for (int step = 0; step < NSTEPS; step++) {
        unsigned indmask = 0;

        // ---- stage 1: propose flips, forward log-prob terms ----
        #pragma unroll
        for (int m = 0; m < Mrows; m++) {
            float rv  = __ldcs(&rr[((size_t)(step * Bm + rowBase + m)) * Dm + d]);
            float nv  = __ldcs(&noise[((size_t)(step * Bm + rowBase + m)) * Dm + d]);
            float hm  = xh[m * Dm + d];
            float xf  = ((xmask >> m) & 1u) ? 1.0f : 0.0f;
            float sgn = 1.0f - 2.0f * xf;                    // -(2x-1)
            float ga  = (xf - xa[m]) * 1e-4f;                // (x - xa)/ETA
            float hb  = hm + bd;
            float gm  = (hb * sgn) * 0.5f - (ga * 0.5f) * sgn;
            float fp  = my_sigmoid(gm - 2.5f);
            bool ind  = rv < fp;
            float inner = xa[m] + 0.25f * ga;
            float pn  = __fmul_rn(0.70710678118654752f, nv);
            float xdav = inner + pn;
            float lpf = my_log((ind ? fp : 1.0f - fp) + 1e-10f);
            float e1  = (xf != 0.0f) ? fmaf(0.5f, hm, bd) : 0.0f;  // x*(0.5h+b)
            float dxa = xf - xa[m];
            float q1  = xdav - inner;
            taccs[m][d] = fmaf(dxa * dxa, 5e-5f, q1 * q1) - lpf - e1;
            if (ind) indmask |= (1u << m);
            unsigned pb = __ballot_sync(0xffffffffu, ind && xf == 0.0f);
            unsigned nb = __ballot_sync(0xffffffffu, ind && xf != 0.0f);
            if (lane == 0) { posw[m][warp] = pb; negw[m][warp] = nb; }
            xdas[m][d] = xdav;
        }
        __syncthreads();

        // ---- stage 1b: expand bitmasks into per-row packed flip lists ----
        // Order: chunk 0..7, pos asc then neg asc per chunk (bit-identical h2 order).
        if (d < Mrows * NW) {
            int m = d >> 3, c = d & 7;
            int off = 0;
            #pragma unroll
            for (int c2 = 0; c2 < NW; c2++) {
                int cnt = __popc(posw[m][c2]) + __popc(negw[m][c2]);
                if (c2 < c) off += cnt;
            }
            int base = c * 32;
            unsigned pw = posw[m][c];
            while (pw) { int j = __ffs(pw) - 1; pw &= pw - 1; flist[m][off++] = (base + j) << 10; }
            unsigned nw_ = negw[m][c];
            while (nw_) { int j = __ffs(nw_) - 1; nw_ &= nw_ - 1; flist[m][off++] = (int)(SIGNB | (unsigned)((base + j) << 10)); }
            if (c == NW - 1) {
                int padded = (off + 3) & ~3;
                for (int i = off; i < padded; i++) flist[m][i] = PADB;
                fcnt[m] = off;
            }
        }
        __syncthreads();

        // ---- stage 2a: float4 gather (+ L2 prefetch of next step's streams) ----
        {
            if (lane == 0 && step + 1 < NSTEPS) {
                size_t basep = ((size_t)((step + 1) * Bm + rowBase)) * Dm + (warp << 5);
                #pragma unroll
                for (int m = 0; m < Mrows; m++) {
                    asm volatile("prefetch.global.L2 [%0];" :: "l"(rr + basep + (size_t)m * Dm));
                    asm volatile("prefetch.global.L2 [%0];" :: "l"(noise + basep + (size_t)m * Dm));
                }
            }
            const int g  = d & 63;
            const int rp = d >> 6;
            const char* wbase = (const char*)Wm + g * 16;
            #pragma unroll
            for (int t = 0; t < 2; t++) {
                const int m = rp + t * 4;
                const int cnt  = fcnt[m];
                const int full = cnt & ~3;
                const int* fl = flist[m];
                const int4* fl4 = reinterpret_cast<const int4*>(fl);
                float4 acc = *reinterpret_cast<const float4*>(&xh[m * Dm + g * 4]);
                int4 en = fl4[0];
                for (int i = 0; i < full; i += 4) {
                    int4 e = en;
                    en = fl4[(i >> 2) + 1];
                    float4 w0 = *reinterpret_cast<const float4*>(wbase + (e.x & OFFM));
                    float4 w1 = *reinterpret_cast<const float4*>(wbase + (e.y & OFFM));
                    float4 w2 = *reinterpret_cast<const float4*>(wbase + (e.z & OFFM));
                    float4 w3 = *reinterpret_cast<const float4*>(wbase + (e.w & OFFM));
                    acc.x += sxor(w0.x, e.x); acc.y += sxor(w0.y, e.x);
                    acc.z += sxor(w0.z, e.x); acc.w += sxor(w0.w, e.x);
                    acc.x += sxor(w1.x, e.y); acc.y += sxor(w1.y, e.y);
                    acc.z += sxor(w1.z, e.y); acc.w += sxor(w1.w, e.y);
                    acc.x += sxor(w2.x, e.z); acc.y += sxor(w2.y, e.z);
                    acc.z += sxor(w2.z, e.z); acc.w += sxor(w2.w, e.z);
                    acc.x += sxor(w3.x, e.w); acc.y += sxor(w3.y, e.w);
                    acc.z += sxor(w3.z, e.w); acc.w += sxor(w3.w, e.w);
                }
                if (cnt & 3) {   // one padded tail group: fmaf(sv in {+1,-1,0}) exact
                    #pragma unroll
                    for (int j = 0; j < 4; j++) {
                        int e = fl[full + j];
                        float sv = (e & PADB) ? 0.0f : ((e < 0) ? -1.0f : 1.0f);
                        float4 w = *reinterpret_cast<const float4*>(wbase + (e & OFFM));
                        acc.x = fmaf(sv, w.x, acc.x);
                        acc.y = fmaf(sv, w.y, acc.y);
                        acc.z = fmaf(sv, w.z, acc.z);
                        acc.w = fmaf(sv, w.w, acc.w);
                    }
                }
                *reinterpret_cast<float4*>(&h2s[m][g * 4]) = acc;
            }
        }
        __syncthreads();

        // ---- stage 2b: reverse terms + per-row la reduce (owner thread d) ----
        #pragma unroll
        for (int m = 0; m < Mrows; m++) {
            float acc  = h2s[m][d];
            float xdav = xdas[m][d];
            float xf   = ((xmask >> m) & 1u) ? 1.0f : 0.0f;
            bool  ind  = (indmask >> m) & 1u;
            float xdv  = ind ? 1.0f - xf : xf;
            float sgn2 = 1.0f - 2.0f * xdv;
            float ga2  = (xdv - xdav) * 1e-4f;
            float hb2  = acc + bd;
            float gm2  = (hb2 * sgn2) * 0.5f - (ga2 * 0.5f) * sgn2;
            float fp2  = my_sigmoid(gm2 - 2.5f);
            float lpr  = my_log((ind ? fp2 : 1.0f - fp2) + 1e-10f);
            float e2   = (xdv != 0.0f) ? fmaf(0.5f, acc, bd) : 0.0f;
            float dxd  = xdv - xdav;
            float inner2 = fmaf(0.25f, ga2, xdav);
            float q2   = xa[m] - inner2;
            float t = taccs[m][d] + lpr + e2 - fmaf(dxd * dxd, 5e-5f, q2 * q2);

            t += __shfl_down_sync(0xffffffffu, t, 16);
            t += __shfl_down_sync(0xffffffffu, t, 8);
            t += __shfl_down_sync(0xffffffffu, t, 4);
            t += __shfl_down_sync(0xffffffffu, t, 2);
            t += __shfl_down_sync(0xffffffffu, t, 1);
            if (lane == 0) red[m][warp] = t;
        }
        __syncthreads();

        // ---- MH accept per row ----
        if (d < Mrows) {
            float la = 0.0f;
            #pragma unroll
            for (int w2 = 0; w2 < NW; w2++) la += red[d][w2];
            float u = __ldcs(&au[step * Bm + rowBase + d]);
            float lu = (u > 0.0f) ? my_log(u) : -3.0e38f;
            accs[d] = (la > lu) ? 1.0f : 0.0f;
        }
        __syncthreads();

        // ---- commit (thread-private slots only; next barrier is after stage 1) ----
        #pragma unroll
        for (int m = 0; m < Mrows; m++) {
            if (accs[m] != 0.0f) {
                xa[m] = xdas[m][d];
                xh[m * Dm + d] = h2s[m][d];
                xmask ^= (indmask & (1u << m));
            }
        }
        // no __syncthreads here: commit wrote only this thread's own xh/xa slots;
        // the cross-thread readers (stage 2a) are behind the stage-1-end barrier.
    }

    #pragma unroll
    for (int m = 0; m < Mrows; m++) {
        float xf = ((xmask >> m) & 1u) ? 1.0f : 0.0f;
        __stcs(&out[(size_t)(rowBase + m) * Dm + d], xf);
        __stcs(&out[(size_t)Bm * Dm + (size_t)(rowBase + m) * Dm + d], xa[m]);
    }
}

extern "C" void kernel_launch(void* const* d_in, const int* in_sizes, int n_in,
                              void* d_out, int out_size) {
    const float* x  = (const float*)d_in[0];
    const float* xa = (const float*)d_in[1];
    const float* W  = (const float*)d_in[2];
    const float* b  = (const float*)d_in[3];
    const float* rr = (const float*)d_in[4];
    const float* nz = (const float*)d_in[5];
    const float* au = (const float*)d_in[6];
    els_kernel<<<Bm / Mrows, 256>>>(x, xa, W, b, rr, nz, au, (float*)d_out);
}